// round 11
// baseline (speedup 1.0000x reference)
#include <cuda_runtime.h>
#include <cuda_fp16.h>
#include <math.h>

#define NN 100000
#define EE 1600000
#define TT 4
#define NLOCK 15
#define TN (TT * NN)
#define CAP 64            // bucket capacity; P(Poisson(16) >= 64) ~ 2e-18

// ---------------- static device scratch ----------------
// Node row = 32B, split into two SELF-CONTAINED 16B head-halves:
//   row[2i+h] = { es_h (fp32), h_{6h+0..1}, h_{6h+2..3}, h_{6h+4..5} (fp16 pairs) }
__device__ float4 g_rowA[TN * 2];
__device__ float4 g_rowB[TN * 2];
__device__ float2 g_edA[TN];
__device__ float2 g_edB[TN];
__device__ int    g_cnt[TN];
__device__ int    g_bkt[(size_t)TN * CAP];   // padded per-(t,node) src buckets
__device__ double g_sum[TT];
__device__ double g_sumsq[TT];
__device__ float  g_stats[TT * 2];

__device__ __forceinline__ float lrelu(float x) { return x > 0.f ? x : 0.2f * x; }

__device__ __forceinline__ float2 up2(float f) {
    unsigned u = __float_as_uint(f);
    __half2 h = *reinterpret_cast<__half2*>(&u);
    return __half22float2(h);
}
__device__ __forceinline__ float pk2(float a, float b) {
    __half2 h = __floats2half2_rn(a, b);
    return __uint_as_float(*reinterpret_cast<unsigned*>(&h));
}

// ---------------- fused zero: stats + cnt ----------------
__global__ void zero_kernel() {
    int i = blockIdx.x * blockDim.x + threadIdx.x;
    if (i < TN) g_cnt[i] = 0;
    if (i < TT) { g_sum[i] = 0.0; g_sumsq[i] = 0.0; }
}

__global__ void reduce_req_kernel(const float* __restrict__ req) {
    const int t = blockIdx.y;
    const int M = NN - NLOCK;
    double s = 0.0, ss = 0.0;
    for (int i = blockIdx.x * blockDim.x + threadIdx.x; i < M; i += gridDim.x * blockDim.x) {
        double v = (double)req[t * NN + NLOCK + i];
        s += v; ss += v * v;
    }
    #pragma unroll
    for (int o = 16; o > 0; o >>= 1) {
        s  += __shfl_down_sync(0xFFFFFFFFu, s,  o);
        ss += __shfl_down_sync(0xFFFFFFFFu, ss, o);
    }
    __shared__ double shs[8], shss[8];
    int w = threadIdx.x >> 5, l = threadIdx.x & 31;
    if (l == 0) { shs[w] = s; shss[w] = ss; }
    __syncthreads();
    if (threadIdx.x == 0) {
        double S = 0.0, SS = 0.0;
        int nw = blockDim.x >> 5;
        for (int i = 0; i < nw; i++) { S += shs[i]; SS += shss[i]; }
        atomicAdd(&g_sum[t], S);
        atomicAdd(&g_sumsq[t], SS);
    }
}

__global__ void finalize_stats_kernel() {
    int t = threadIdx.x;
    if (t < TT) {
        double n = (double)(NN - NLOCK);
        double mean = g_sum[t] / n;
        double var = (g_sumsq[t] - g_sum[t] * mean) / (n - 1.0);
        g_stats[2 * t]     = (float)mean;
        g_stats[2 * t + 1] = (float)(1.0 / sqrt(var));
    }
}

// ---------------- bucket scatter: 4 edges/thread ----------------
__global__ void scatter_kernel(const int* __restrict__ ei) {
    int q = blockIdx.x * blockDim.x + threadIdx.x;   // quad index
    int t = blockIdx.y;
    if (q >= EE / 4) return;
    const int* b = ei + (size_t)t * 2 * EE;
    int4 s4 = *(const int4*)(b + q * 4);
    int4 d4 = *(const int4*)(b + EE + q * 4);
    int g0 = t * NN + d4.x, g1 = t * NN + d4.y, g2 = t * NN + d4.z, g3 = t * NN + d4.w;
    int p0 = atomicAdd(&g_cnt[g0], 1);
    int p1 = atomicAdd(&g_cnt[g1], 1);
    int p2 = atomicAdd(&g_cnt[g2], 1);
    int p3 = atomicAdd(&g_cnt[g3], 1);
    g_bkt[(size_t)g0 * CAP + p0] = s4.x;
    g_bkt[(size_t)g1 * CAP + p1] = s4.y;
    g_bkt[(size_t)g2 * CAP + p2] = s4.z;
    g_bkt[(size_t)g3 * CAP + p3] = s4.w;
}

// ---------------- layer 0: build x from inputs, project, write head-split rows ----
__global__ void node0_kernel(const int* __restrict__ nt,
                             const float* __restrict__ req,
                             const float* __restrict__ ti,
                             const float* __restrict__ emb,
                             const float* __restrict__ W,
                             const float* __restrict__ as_,
                             const float* __restrict__ ad_) {
    __shared__ float sW[5 * 12];
    __shared__ float sas[12], sad[12];
    for (int i = threadIdx.x; i < 5 * 12; i += blockDim.x) sW[i] = W[i];
    if (threadIdx.x < 12) { sas[threadIdx.x] = as_[threadIdx.x]; sad[threadIdx.x] = ad_[threadIdx.x]; }
    __syncthreads();
    int idx = blockIdx.x * blockDim.x + threadIdx.x;
    if (idx >= TN) return;
    int t = idx / NN;
    int n = idx - t * NN;
    float mean = g_stats[2 * t], rstd = g_stats[2 * t + 1];
    int type = nt[idx];
    float r = req[idx];
    float xv[5];
    xv[0] = __ldg(&emb[type * 3 + 0]);
    xv[1] = __ldg(&emb[type * 3 + 1]);
    xv[2] = __ldg(&emb[type * 3 + 2]);
    xv[3] = (n < NLOCK) ? r : (r - mean) * rstd;
    xv[4] = ti[idx];

    float h[12];
    #pragma unroll
    for (int j = 0; j < 12; j++) {
        float a = 0.f;
        #pragma unroll
        for (int k = 0; k < 5; k++) a = fmaf(xv[k], sW[k * 12 + j], a);
        h[j] = a;
    }
    float es0 = 0.f, es1 = 0.f, ed0 = 0.f, ed1 = 0.f;
    #pragma unroll
    for (int c = 0; c < 6; c++) {
        es0 = fmaf(h[c],     sas[c],     es0);
        es1 = fmaf(h[6 + c], sas[6 + c], es1);
        ed0 = fmaf(h[c],     sad[c],     ed0);
        ed1 = fmaf(h[6 + c], sad[6 + c], ed1);
    }
    // head-split halves
    g_rowA[(size_t)idx * 2]     = make_float4(es0, pk2(h[0], h[1]), pk2(h[2], h[3]), pk2(h[4], h[5]));
    g_rowA[(size_t)idx * 2 + 1] = make_float4(es1, pk2(h[6], h[7]), pk2(h[8], h[9]), pk2(h[10], h[11]));
    g_edA[idx] = make_float2(ed0, ed1);
}

// ---------------- fused gather + softmax + (bias/relu) + next projection ----------
// 16 lanes per node: lane = head*8 + slot (slot 0..7, stride-8 interleave).
// Each lane loads self-contained 16B head-halves (1 LDG.128/edge-half); the two
// head lanes of an edge hit the same 128B line -> 1 wavefront/edge. Avg ~2
// iterations/lane halves the serial L2 chain vs 8 lanes/node.
template <bool FINAL, bool A_TO_B>
__global__ void gather_kernel(const float* __restrict__ bcur,
                              const float* __restrict__ Wn,
                              const float* __restrict__ asn,
                              const float* __restrict__ adn,
                              float* __restrict__ outp) {
    __shared__ float sW[144], sas[12], sad[12], sb[12];
    if (!FINAL) {
        for (int k = threadIdx.x; k < 144; k += blockDim.x) sW[k] = Wn[k];
        if (threadIdx.x < 12) { sas[threadIdx.x] = asn[threadIdx.x]; sad[threadIdx.x] = adn[threadIdx.x]; }
    }
    if (threadIdx.x < 12) sb[threadIdx.x] = bcur[threadIdx.x];
    __syncthreads();

    const float4* rows_in  = A_TO_B ? g_rowA : g_rowB;
    const float2* ed_in    = A_TO_B ? g_edA  : g_edB;
    float4*       rows_out = A_TO_B ? g_rowB : g_rowA;
    float2*       ed_out   = A_TO_B ? g_edB  : g_edA;

    int gt   = blockIdx.x * blockDim.x + threadIdx.x;
    int i    = gt >> 4;                    // global node
    int lane = gt & 15;
    int head = lane >> 3;                  // 0 or 1
    int slot = lane & 7;                   // stride-8 slot
    int t    = i / NN;
    int nloc = i - t * NN;
    const float4* tbase = rows_in + (size_t)t * NN * 2 + head;

    float2 edv = ed_in[i];
    float ed_mine = head ? edv.y : edv.x;

    float a0 = 0.f, a1 = 0.f, a2 = 0.f, a3 = 0.f, a4 = 0.f, a5 = 0.f, aden = 0.f;

    auto process = [&](int src) {
        float4 q = tbase[(size_t)src * 2];
        float p = __expf(lrelu(q.x + ed_mine));
        float2 u = up2(q.y), v = up2(q.z), w = up2(q.w);
        a0 = fmaf(u.x, p, a0); a1 = fmaf(u.y, p, a1);
        a2 = fmaf(v.x, p, a2); a3 = fmaf(v.y, p, a3);
        a4 = fmaf(w.x, p, a4); a5 = fmaf(w.y, p, a5);
        aden += p;
    };

    int cnt = g_cnt[i];
    const int* bkt = &g_bkt[(size_t)i * CAP];

    if (slot == 0) process(nloc);          // self loop

    #pragma unroll 2
    for (int j = slot; j < cnt; j += 8) {
        process(bkt[j]);
    }

    __syncwarp();
    // reduce within the 8 slots of this head
    #pragma unroll
    for (int o2 = 1; o2 < 8; o2 <<= 1) {
        a0 += __shfl_xor_sync(0xFFFFFFFFu, a0, o2);
        a1 += __shfl_xor_sync(0xFFFFFFFFu, a1, o2);
        a2 += __shfl_xor_sync(0xFFFFFFFFu, a2, o2);
        a3 += __shfl_xor_sync(0xFFFFFFFFu, a3, o2);
        a4 += __shfl_xor_sync(0xFFFFFFFFu, a4, o2);
        a5 += __shfl_xor_sync(0xFFFFFFFFu, a5, o2);
        aden += __shfl_xor_sync(0xFFFFFFFFu, aden, o2);
    }
    // exchange heads (xor 8)
    float b0 = __shfl_xor_sync(0xFFFFFFFFu, a0, 8);
    float b1 = __shfl_xor_sync(0xFFFFFFFFu, a1, 8);
    float b2 = __shfl_xor_sync(0xFFFFFFFFu, a2, 8);
    float b3 = __shfl_xor_sync(0xFFFFFFFFu, a3, 8);
    float b4 = __shfl_xor_sync(0xFFFFFFFFu, a4, 8);
    float b5 = __shfl_xor_sync(0xFFFFFFFFu, a5, 8);
    float bden = __shfl_xor_sync(0xFFFFFFFFu, aden, 8);

    float num[12], den0, den1;
    if (head == 0) {
        num[0]=a0; num[1]=a1; num[2]=a2; num[3]=a3; num[4]=a4; num[5]=a5;
        num[6]=b0; num[7]=b1; num[8]=b2; num[9]=b3; num[10]=b4; num[11]=b5;
        den0 = aden; den1 = bden;
    } else {
        num[0]=b0; num[1]=b1; num[2]=b2; num[3]=b3; num[4]=b4; num[5]=b5;
        num[6]=a0; num[7]=a1; num[8]=a2; num[9]=a3; num[10]=a4; num[11]=a5;
        den0 = bden; den1 = aden;
    }

    float r0 = 1.f / (den0 + 1e-16f);
    float r1 = 1.f / (den1 + 1e-16f);
    float o[12];
    #pragma unroll
    for (int k = 0; k < 12; k++) {
        float v = num[k] * ((k < 6) ? r0 : r1) + sb[k];
        o[k] = FINAL ? v : fmaxf(v, 0.f);
    }

    if (FINAL) {
        if (lane < 3) {
            float4* dp = (float4*)(outp + (size_t)i * 12);
            dp[lane] = make_float4(o[lane * 4], o[lane * 4 + 1], o[lane * 4 + 2], o[lane * 4 + 3]);
        }
    } else {
        // lanes 0..3 compute 3 output columns each (cols lane*3 .. lane*3+2)
        float hc[3] = {0.f, 0.f, 0.f};
        float es0 = 0.f, es1 = 0.f, ep0 = 0.f, ep1 = 0.f;
        if (lane < 4) {
            #pragma unroll
            for (int jj = 0; jj < 3; jj++) {
                int jc = lane * 3 + jj;
                float a = 0.f;
                #pragma unroll
                for (int k = 0; k < 12; k++) a = fmaf(o[k], sW[k * 12 + jc], a);
                hc[jj] = a;
                if (jc < 6) { es0 = fmaf(a, sas[jc], es0); ep0 = fmaf(a, sad[jc], ep0); }
                else        { es1 = fmaf(a, sas[jc], es1); ep1 = fmaf(a, sad[jc], ep1); }
            }
        }
        // reduce es/ed partials over the 16 lanes of this node
        #pragma unroll
        for (int o2 = 1; o2 < 16; o2 <<= 1) {
            es0 += __shfl_xor_sync(0xFFFFFFFFu, es0, o2);
            es1 += __shfl_xor_sync(0xFFFFFFFFu, es1, o2);
            ep0 += __shfl_xor_sync(0xFFFFFFFFu, ep0, o2);
            ep1 += __shfl_xor_sync(0xFFFFFFFFu, ep1, o2);
        }
        // partner columns: lane0 gets lane1's cols 3-5; lane2 gets lane3's cols 9-11
        float q0 = __shfl_xor_sync(0xFFFFFFFFu, hc[0], 1);
        float q1 = __shfl_xor_sync(0xFFFFFFFFu, hc[1], 1);
        float q2 = __shfl_xor_sync(0xFFFFFFFFu, hc[2], 1);

        if (lane == 0) {
            rows_out[(size_t)i * 2] = make_float4(es0, pk2(hc[0], hc[1]),
                                                  pk2(hc[2], q0), pk2(q1, q2));
        } else if (lane == 2) {
            rows_out[(size_t)i * 2 + 1] = make_float4(es1, pk2(hc[0], hc[1]),
                                                      pk2(hc[2], q0), pk2(q1, q2));
        } else if (lane == 4) {
            ed_out[i] = make_float2(ep0, ep1);
        }
    }
}

// ---------------- launch ----------------
extern "C" void kernel_launch(void* const* d_in, const int* in_sizes, int n_in,
                              void* d_out, int out_size) {
    const int*   node_types = (const int*)d_in[0];
    const float* requests   = (const float*)d_in[1];
    const float* time_index = (const float*)d_in[2];
    const int*   edge_index = (const int*)d_in[3];
    const float* emb        = (const float*)d_in[4];
    float* out = (float*)d_out;

    const int BT = 256;
    const int node_blocks = (TN + BT - 1) / BT;
    dim3 sc_grid((EE / 4 + BT - 1) / BT, TT);
    const int gather_blocks = (TN * 16) / BT;    // 25000 exact

    zero_kernel<<<node_blocks, BT>>>();
    { dim3 grid(128, TT); reduce_req_kernel<<<grid, BT>>>(requests); }
    finalize_stats_kernel<<<1, 32>>>();

    scatter_kernel<<<sc_grid, BT>>>(edge_index);

    node0_kernel<<<node_blocks, BT>>>(node_types, requests, time_index, emb,
                                      (const float*)d_in[5], (const float*)d_in[6],
                                      (const float*)d_in[7]);

    gather_kernel<false, true ><<<gather_blocks, BT>>>(
        (const float*)d_in[8],  (const float*)d_in[9],
        (const float*)d_in[10], (const float*)d_in[11], nullptr);
    gather_kernel<false, false><<<gather_blocks, BT>>>(
        (const float*)d_in[12], (const float*)d_in[13],
        (const float*)d_in[14], (const float*)d_in[15], nullptr);
    gather_kernel<false, true ><<<gather_blocks, BT>>>(
        (const float*)d_in[16], (const float*)d_in[17],
        (const float*)d_in[18], (const float*)d_in[19], nullptr);
    gather_kernel<true,  false><<<gather_blocks, BT>>>(
        (const float*)d_in[20], nullptr, nullptr, nullptr, out);
}

// round 12
// speedup vs baseline: 1.5188x; 1.5188x over previous
#include <cuda_runtime.h>
#include <cuda_fp16.h>
#include <math.h>

#define NN 100000
#define EE 1600000
#define TT 4
#define NLOCK 15
#define TN (TT * NN)
#define CAP 64            // bucket capacity; P(Poisson(16) >= 64) ~ 2e-18

// ---------------- static device scratch ----------------
// Node row = 32B, split into two SELF-CONTAINED 16B head-halves:
//   row[2i+h] = { es_h (fp32), h_{6h+0..1}, h_{6h+2..3}, h_{6h+4..5} (fp16 pairs) }
__device__ float4 g_rowA[TN * 2];
__device__ float4 g_rowB[TN * 2];
__device__ float2 g_edA[TN];
__device__ float2 g_edB[TN];
__device__ int    g_cnt[TN];
__device__ int    g_bkt[(size_t)TN * CAP];   // padded per-(t,node) src buckets
__device__ double g_sum[TT];
__device__ double g_sumsq[TT];
__device__ float  g_stats[TT * 2];

__device__ __forceinline__ float lrelu(float x) { return x > 0.f ? x : 0.2f * x; }

__device__ __forceinline__ float2 up2(float f) {
    unsigned u = __float_as_uint(f);
    __half2 h = *reinterpret_cast<__half2*>(&u);
    return __half22float2(h);
}
__device__ __forceinline__ float pk2(float a, float b) {
    __half2 h = __floats2half2_rn(a, b);
    return __uint_as_float(*reinterpret_cast<unsigned*>(&h));
}

// ---------------- fused zero: stats + cnt ----------------
__global__ void zero_kernel() {
    int i = blockIdx.x * blockDim.x + threadIdx.x;
    if (i < TN) g_cnt[i] = 0;
    if (i < TT) { g_sum[i] = 0.0; g_sumsq[i] = 0.0; }
}

// ---------------- fused scatter + reduce_req ----------------
// Blocks [0, 512): request-stats reduction (scheduled first, ~10us, SM-bound).
// Blocks [512, 512+6252): bucket scatter (80us, LTS-bound, issue ~3%).
// The two roles co-schedule; reduce work hides under scatter's L2 latency.
#define RED_BLOCKS 512           // 128 blocks x TT timesteps
#define SC_BLOCKS_PER_T 1563     // ceil(EE/4 / 256)
__global__ void scatter_reduce_kernel(const int* __restrict__ ei,
                                      const float* __restrict__ req) {
    if (blockIdx.x < RED_BLOCKS) {
        // ---- reduce role ----
        const int t = blockIdx.x >> 7;            // 128 blocks per t
        const int bx = blockIdx.x & 127;
        const int M = NN - NLOCK;
        double s = 0.0, ss = 0.0;
        for (int i = bx * blockDim.x + threadIdx.x; i < M; i += 128 * blockDim.x) {
            double v = (double)req[t * NN + NLOCK + i];
            s += v; ss += v * v;
        }
        #pragma unroll
        for (int o = 16; o > 0; o >>= 1) {
            s  += __shfl_down_sync(0xFFFFFFFFu, s,  o);
            ss += __shfl_down_sync(0xFFFFFFFFu, ss, o);
        }
        __shared__ double shs[8], shss[8];
        int w = threadIdx.x >> 5, l = threadIdx.x & 31;
        if (l == 0) { shs[w] = s; shss[w] = ss; }
        __syncthreads();
        if (threadIdx.x == 0) {
            double S = 0.0, SS = 0.0;
            int nw = blockDim.x >> 5;
            for (int i = 0; i < nw; i++) { S += shs[i]; SS += shss[i]; }
            atomicAdd(&g_sum[t], S);
            atomicAdd(&g_sumsq[t], SS);
        }
    } else {
        // ---- scatter role: 4 edges/thread ----
        int sblk = blockIdx.x - RED_BLOCKS;
        int t = sblk / SC_BLOCKS_PER_T;
        int q = (sblk - t * SC_BLOCKS_PER_T) * blockDim.x + threadIdx.x;
        if (q >= EE / 4) return;
        const int* b = ei + (size_t)t * 2 * EE;
        int4 s4 = *(const int4*)(b + q * 4);
        int4 d4 = *(const int4*)(b + EE + q * 4);
        int g0 = t * NN + d4.x, g1 = t * NN + d4.y, g2 = t * NN + d4.z, g3 = t * NN + d4.w;
        int p0 = atomicAdd(&g_cnt[g0], 1);
        int p1 = atomicAdd(&g_cnt[g1], 1);
        int p2 = atomicAdd(&g_cnt[g2], 1);
        int p3 = atomicAdd(&g_cnt[g3], 1);
        g_bkt[(size_t)g0 * CAP + p0] = s4.x;
        g_bkt[(size_t)g1 * CAP + p1] = s4.y;
        g_bkt[(size_t)g2 * CAP + p2] = s4.z;
        g_bkt[(size_t)g3 * CAP + p3] = s4.w;
    }
}

__global__ void finalize_stats_kernel() {
    int t = threadIdx.x;
    if (t < TT) {
        double n = (double)(NN - NLOCK);
        double mean = g_sum[t] / n;
        double var = (g_sumsq[t] - g_sum[t] * mean) / (n - 1.0);
        g_stats[2 * t]     = (float)mean;
        g_stats[2 * t + 1] = (float)(1.0 / sqrt(var));
    }
}

// ---------------- layer 0: build x from inputs, project, write head-split rows ----
__global__ void node0_kernel(const int* __restrict__ nt,
                             const float* __restrict__ req,
                             const float* __restrict__ ti,
                             const float* __restrict__ emb,
                             const float* __restrict__ W,
                             const float* __restrict__ as_,
                             const float* __restrict__ ad_) {
    __shared__ float sW[5 * 12];
    __shared__ float sas[12], sad[12];
    for (int i = threadIdx.x; i < 5 * 12; i += blockDim.x) sW[i] = W[i];
    if (threadIdx.x < 12) { sas[threadIdx.x] = as_[threadIdx.x]; sad[threadIdx.x] = ad_[threadIdx.x]; }
    __syncthreads();
    int idx = blockIdx.x * blockDim.x + threadIdx.x;
    if (idx >= TN) return;
    int t = idx / NN;
    int n = idx - t * NN;
    float mean = g_stats[2 * t], rstd = g_stats[2 * t + 1];
    int type = nt[idx];
    float r = req[idx];
    float xv[5];
    xv[0] = __ldg(&emb[type * 3 + 0]);
    xv[1] = __ldg(&emb[type * 3 + 1]);
    xv[2] = __ldg(&emb[type * 3 + 2]);
    xv[3] = (n < NLOCK) ? r : (r - mean) * rstd;
    xv[4] = ti[idx];

    float h[12];
    #pragma unroll
    for (int j = 0; j < 12; j++) {
        float a = 0.f;
        #pragma unroll
        for (int k = 0; k < 5; k++) a = fmaf(xv[k], sW[k * 12 + j], a);
        h[j] = a;
    }
    float es0 = 0.f, es1 = 0.f, ed0 = 0.f, ed1 = 0.f;
    #pragma unroll
    for (int c = 0; c < 6; c++) {
        es0 = fmaf(h[c],     sas[c],     es0);
        es1 = fmaf(h[6 + c], sas[6 + c], es1);
        ed0 = fmaf(h[c],     sad[c],     ed0);
        ed1 = fmaf(h[6 + c], sad[6 + c], ed1);
    }
    // head-split halves
    g_rowA[(size_t)idx * 2]     = make_float4(es0, pk2(h[0], h[1]), pk2(h[2], h[3]), pk2(h[4], h[5]));
    g_rowA[(size_t)idx * 2 + 1] = make_float4(es1, pk2(h[6], h[7]), pk2(h[8], h[9]), pk2(h[10], h[11]));
    g_edA[idx] = make_float2(ed0, ed1);
}

// ---------------- fused gather + softmax + (bias/relu) + next projection ----------
// 8 lanes per node: lane = head*4 + slot (stride-4 interleave, unroll 4).
// Each lane loads ONE self-contained 16B head-half per edge (1 LDG.128); head
// pair hits same 128B line -> 1 L1tex wavefront per edge. No intra-loop shfls.
template <bool FINAL, bool A_TO_B>
__global__ void gather_kernel(const float* __restrict__ bcur,
                              const float* __restrict__ Wn,
                              const float* __restrict__ asn,
                              const float* __restrict__ adn,
                              float* __restrict__ outp) {
    __shared__ float sW[144], sas[12], sad[12], sb[12];
    if (!FINAL) {
        for (int k = threadIdx.x; k < 144; k += blockDim.x) sW[k] = Wn[k];
        if (threadIdx.x < 12) { sas[threadIdx.x] = asn[threadIdx.x]; sad[threadIdx.x] = adn[threadIdx.x]; }
    }
    if (threadIdx.x < 12) sb[threadIdx.x] = bcur[threadIdx.x];
    __syncthreads();

    const float4* rows_in  = A_TO_B ? g_rowA : g_rowB;
    const float2* ed_in    = A_TO_B ? g_edA  : g_edB;
    float4*       rows_out = A_TO_B ? g_rowB : g_rowA;
    float2*       ed_out   = A_TO_B ? g_edB  : g_edA;

    int gt   = blockIdx.x * blockDim.x + threadIdx.x;
    int i    = gt >> 3;                    // global node
    int lane = gt & 7;
    int head = lane >> 2;                  // 0 or 1
    int slot = lane & 3;                   // stride-4 slot
    int t    = i / NN;
    int nloc = i - t * NN;
    const float4* tbase = rows_in + (size_t)t * NN * 2 + head;

    float2 edv = ed_in[i];
    float ed_mine = head ? edv.y : edv.x;

    float a0 = 0.f, a1 = 0.f, a2 = 0.f, a3 = 0.f, a4 = 0.f, a5 = 0.f, aden = 0.f;

    auto process = [&](int src) {
        float4 q = tbase[(size_t)src * 2];
        float p = __expf(lrelu(q.x + ed_mine));
        float2 u = up2(q.y), v = up2(q.z), w = up2(q.w);
        a0 = fmaf(u.x, p, a0); a1 = fmaf(u.y, p, a1);
        a2 = fmaf(v.x, p, a2); a3 = fmaf(v.y, p, a3);
        a4 = fmaf(w.x, p, a4); a5 = fmaf(w.y, p, a5);
        aden += p;
    };

    int cnt = g_cnt[i];
    const int* bkt = &g_bkt[(size_t)i * CAP];

    if (slot == 0) process(nloc);          // self loop

    #pragma unroll 4
    for (int j = slot; j < cnt; j += 4) {
        process(bkt[j]);
    }

    // reduce within the 4 slots of this head
    #pragma unroll
    for (int o2 = 1; o2 < 4; o2 <<= 1) {
        a0 += __shfl_xor_sync(0xFFFFFFFFu, a0, o2);
        a1 += __shfl_xor_sync(0xFFFFFFFFu, a1, o2);
        a2 += __shfl_xor_sync(0xFFFFFFFFu, a2, o2);
        a3 += __shfl_xor_sync(0xFFFFFFFFu, a3, o2);
        a4 += __shfl_xor_sync(0xFFFFFFFFu, a4, o2);
        a5 += __shfl_xor_sync(0xFFFFFFFFu, a5, o2);
        aden += __shfl_xor_sync(0xFFFFFFFFu, aden, o2);
    }
    // exchange heads (xor 4)
    float b0 = __shfl_xor_sync(0xFFFFFFFFu, a0, 4);
    float b1 = __shfl_xor_sync(0xFFFFFFFFu, a1, 4);
    float b2 = __shfl_xor_sync(0xFFFFFFFFu, a2, 4);
    float b3 = __shfl_xor_sync(0xFFFFFFFFu, a3, 4);
    float b4 = __shfl_xor_sync(0xFFFFFFFFu, a4, 4);
    float b5 = __shfl_xor_sync(0xFFFFFFFFu, a5, 4);
    float bden = __shfl_xor_sync(0xFFFFFFFFu, aden, 4);

    float num[12], den0, den1;
    if (head == 0) {
        num[0]=a0; num[1]=a1; num[2]=a2; num[3]=a3; num[4]=a4; num[5]=a5;
        num[6]=b0; num[7]=b1; num[8]=b2; num[9]=b3; num[10]=b4; num[11]=b5;
        den0 = aden; den1 = bden;
    } else {
        num[0]=b0; num[1]=b1; num[2]=b2; num[3]=b3; num[4]=b4; num[5]=b5;
        num[6]=a0; num[7]=a1; num[8]=a2; num[9]=a3; num[10]=a4; num[11]=a5;
        den0 = bden; den1 = aden;
    }

    float r0 = 1.f / (den0 + 1e-16f);
    float r1 = 1.f / (den1 + 1e-16f);
    float o[12];
    #pragma unroll
    for (int k = 0; k < 12; k++) {
        float v = num[k] * ((k < 6) ? r0 : r1) + sb[k];
        o[k] = FINAL ? v : fmaxf(v, 0.f);
    }

    if (FINAL) {
        if (lane < 3) {
            float4* dp = (float4*)(outp + (size_t)i * 12);
            dp[lane] = make_float4(o[lane * 4], o[lane * 4 + 1], o[lane * 4 + 2], o[lane * 4 + 3]);
        }
    } else {
        // lanes 0..3 compute 3 output columns each (cols lane*3 .. lane*3+2)
        float hc[3] = {0.f, 0.f, 0.f};
        float es0 = 0.f, es1 = 0.f, ep0 = 0.f, ep1 = 0.f;
        if (lane < 4) {
            #pragma unroll
            for (int jj = 0; jj < 3; jj++) {
                int jc = lane * 3 + jj;
                float a = 0.f;
                #pragma unroll
                for (int k = 0; k < 12; k++) a = fmaf(o[k], sW[k * 12 + jc], a);
                hc[jj] = a;
                if (jc < 6) { es0 = fmaf(a, sas[jc], es0); ep0 = fmaf(a, sad[jc], ep0); }
                else        { es1 = fmaf(a, sas[jc], es1); ep1 = fmaf(a, sad[jc], ep1); }
            }
        }
        #pragma unroll
        for (int o2 = 1; o2 < 8; o2 <<= 1) {
            es0 += __shfl_xor_sync(0xFFFFFFFFu, es0, o2);
            es1 += __shfl_xor_sync(0xFFFFFFFFu, es1, o2);
            ep0 += __shfl_xor_sync(0xFFFFFFFFu, ep0, o2);
            ep1 += __shfl_xor_sync(0xFFFFFFFFu, ep1, o2);
        }
        // partner columns: lane0 gets lane1's cols 3-5; lane2 gets lane3's cols 9-11
        float q0 = __shfl_xor_sync(0xFFFFFFFFu, hc[0], 1);
        float q1 = __shfl_xor_sync(0xFFFFFFFFu, hc[1], 1);
        float q2 = __shfl_xor_sync(0xFFFFFFFFu, hc[2], 1);

        if (lane == 0) {
            rows_out[(size_t)i * 2] = make_float4(es0, pk2(hc[0], hc[1]),
                                                  pk2(hc[2], q0), pk2(q1, q2));
        } else if (lane == 2) {
            rows_out[(size_t)i * 2 + 1] = make_float4(es1, pk2(hc[0], hc[1]),
                                                      pk2(hc[2], q0), pk2(q1, q2));
        } else if (lane == 4) {
            ed_out[i] = make_float2(ep0, ep1);
        }
    }
}

// ---------------- launch ----------------
extern "C" void kernel_launch(void* const* d_in, const int* in_sizes, int n_in,
                              void* d_out, int out_size) {
    const int*   node_types = (const int*)d_in[0];
    const float* requests   = (const float*)d_in[1];
    const float* time_index = (const float*)d_in[2];
    const int*   edge_index = (const int*)d_in[3];
    const float* emb        = (const float*)d_in[4];
    float* out = (float*)d_out;

    const int BT = 256;
    const int node_blocks = (TN + BT - 1) / BT;
    const int sr_blocks = RED_BLOCKS + SC_BLOCKS_PER_T * TT;   // 512 + 6252
    const int gather_blocks = (TN * 8) / BT;                   // 12500 exact

    zero_kernel<<<node_blocks, BT>>>();
    scatter_reduce_kernel<<<sr_blocks, BT>>>(edge_index, requests);
    finalize_stats_kernel<<<1, 32>>>();

    node0_kernel<<<node_blocks, BT>>>(node_types, requests, time_index, emb,
                                      (const float*)d_in[5], (const float*)d_in[6],
                                      (const float*)d_in[7]);

    gather_kernel<false, true ><<<gather_blocks, BT>>>(
        (const float*)d_in[8],  (const float*)d_in[9],
        (const float*)d_in[10], (const float*)d_in[11], nullptr);
    gather_kernel<false, false><<<gather_blocks, BT>>>(
        (const float*)d_in[12], (const float*)d_in[13],
        (const float*)d_in[14], (const float*)d_in[15], nullptr);
    gather_kernel<false, true ><<<gather_blocks, BT>>>(
        (const float*)d_in[16], (const float*)d_in[17],
        (const float*)d_in[18], (const float*)d_in[19], nullptr);
    gather_kernel<true,  false><<<gather_blocks, BT>>>(
        (const float*)d_in[20], nullptr, nullptr, nullptr, out);
}

// round 13
// speedup vs baseline: 1.5277x; 1.0058x over previous
#include <cuda_runtime.h>
#include <cuda_fp16.h>
#include <math.h>

#define NN 100000
#define EE 1600000
#define TT 4
#define NLOCK 15
#define TN (TT * NN)
#define CAP 64            // bucket capacity; P(Poisson(16) >= 64) ~ 2e-18

// ---------------- static device scratch ----------------
// Node row = 32B, split into two SELF-CONTAINED 16B head-halves:
//   row[2i+h] = { es_h (fp32), h_{6h+0..1}, h_{6h+2..3}, h_{6h+4..5} (fp16 pairs) }
__device__ float4 g_rowA[TN * 2];
__device__ float4 g_rowB[TN * 2];
__device__ float2 g_edA[TN];
__device__ float2 g_edB[TN];
__device__ int    g_cnt[TN];
__device__ int    g_bkt[(size_t)TN * CAP];   // padded per-(t,node) src buckets
__device__ double g_sum[TT];
__device__ double g_sumsq[TT];
__device__ int    g_done;                    // reduce-blocks completion counter

__device__ __forceinline__ float lrelu(float x) { return x > 0.f ? x : 0.2f * x; }

__device__ __forceinline__ float2 up2(float f) {
    unsigned u = __float_as_uint(f);
    __half2 h = *reinterpret_cast<__half2*>(&u);
    return __half22float2(h);
}
__device__ __forceinline__ float pk2(float a, float b) {
    __half2 h = __floats2half2_rn(a, b);
    return __uint_as_float(*reinterpret_cast<unsigned*>(&h));
}

// ---------------- zero: cnt (vectorized) + stats + done flag ----------------
__global__ void zero_kernel() {
    int i = blockIdx.x * blockDim.x + threadIdx.x;
    if (i < TN / 4) ((int4*)g_cnt)[i] = make_int4(0, 0, 0, 0);
    if (i < TT) { g_sum[i] = 0.0; g_sumsq[i] = 0.0; }
    if (i == 8) g_done = 0;
}

// ---------------- mega kernel: reduce + scatter + node0 (role-split) ----------
// Blocks [0, RED):                request-stats reduction (wave 1, finishes fast)
// Blocks [RED, RED+SC):           bucket scatter (80us, MSHR/LTS-bound)
// Blocks [RED+SC, RED+SC+NODE0):  layer-0 projection; spins until reduce done
//   (scheduled last in bid order -> reduce blocks long finished; the spin is
//    a formal guard, not a real wait)
#define RED_BLOCKS 512           // 128 blocks x TT timesteps
#define SC_BLOCKS_PER_T 1563     // ceil(EE/4 / 256)
#define SC_BLOCKS (SC_BLOCKS_PER_T * TT)
#define NODE0_BLOCKS 1563        // ceil(TN / 256)
__global__ void mega_kernel(const int* __restrict__ ei,
                            const float* __restrict__ req,
                            const int* __restrict__ nt,
                            const float* __restrict__ ti,
                            const float* __restrict__ emb,
                            const float* __restrict__ W,
                            const float* __restrict__ as_,
                            const float* __restrict__ ad_) {
    if (blockIdx.x < RED_BLOCKS) {
        // ---- reduce role ----
        const int t = blockIdx.x >> 7;            // 128 blocks per t
        const int bx = blockIdx.x & 127;
        const int M = NN - NLOCK;
        double s = 0.0, ss = 0.0;
        for (int i = bx * blockDim.x + threadIdx.x; i < M; i += 128 * blockDim.x) {
            double v = (double)req[t * NN + NLOCK + i];
            s += v; ss += v * v;
        }
        #pragma unroll
        for (int o = 16; o > 0; o >>= 1) {
            s  += __shfl_down_sync(0xFFFFFFFFu, s,  o);
            ss += __shfl_down_sync(0xFFFFFFFFu, ss, o);
        }
        __shared__ double shs[8], shss[8];
        int w = threadIdx.x >> 5, l = threadIdx.x & 31;
        if (l == 0) { shs[w] = s; shss[w] = ss; }
        __syncthreads();
        if (threadIdx.x == 0) {
            double S = 0.0, SS = 0.0;
            int nw = blockDim.x >> 5;
            for (int i = 0; i < nw; i++) { S += shs[i]; SS += shss[i]; }
            atomicAdd(&g_sum[t], S);
            atomicAdd(&g_sumsq[t], SS);
            __threadfence();
            atomicAdd(&g_done, 1);
        }
    } else if (blockIdx.x < RED_BLOCKS + SC_BLOCKS) {
        // ---- scatter role: 4 edges/thread ----
        int sblk = blockIdx.x - RED_BLOCKS;
        int t = sblk / SC_BLOCKS_PER_T;
        int q = (sblk - t * SC_BLOCKS_PER_T) * blockDim.x + threadIdx.x;
        if (q >= EE / 4) return;
        const int* b = ei + (size_t)t * 2 * EE;
        int4 s4 = *(const int4*)(b + q * 4);
        int4 d4 = *(const int4*)(b + EE + q * 4);
        int g0 = t * NN + d4.x, g1 = t * NN + d4.y, g2 = t * NN + d4.z, g3 = t * NN + d4.w;
        int p0 = atomicAdd(&g_cnt[g0], 1);
        int p1 = atomicAdd(&g_cnt[g1], 1);
        int p2 = atomicAdd(&g_cnt[g2], 1);
        int p3 = atomicAdd(&g_cnt[g3], 1);
        g_bkt[(size_t)g0 * CAP + p0] = s4.x;
        g_bkt[(size_t)g1 * CAP + p1] = s4.y;
        g_bkt[(size_t)g2 * CAP + p2] = s4.z;
        g_bkt[(size_t)g3 * CAP + p3] = s4.w;
    } else {
        // ---- node0 role: layer-0 projection ----
        __shared__ float sW[5 * 12];
        __shared__ float sas[12], sad[12];
        __shared__ float smean[TT], srstd[TT];

        // wait for reduce blocks (formally; in practice already done)
        if (threadIdx.x == 0) {
            while (atomicAdd(&g_done, 0) < RED_BLOCKS) { __nanosleep(200); }
        }
        __syncthreads();
        __threadfence();

        for (int i = threadIdx.x; i < 5 * 12; i += blockDim.x) sW[i] = W[i];
        if (threadIdx.x < 12) { sas[threadIdx.x] = as_[threadIdx.x]; sad[threadIdx.x] = ad_[threadIdx.x]; }
        if (threadIdx.x < TT) {
            int t = threadIdx.x;
            double n = (double)(NN - NLOCK);
            double mean = g_sum[t] / n;
            double var = (g_sumsq[t] - g_sum[t] * mean) / (n - 1.0);
            smean[t] = (float)mean;
            srstd[t] = (float)(1.0 / sqrt(var));
        }
        __syncthreads();

        int nb = blockIdx.x - RED_BLOCKS - SC_BLOCKS;
        int idx = nb * blockDim.x + threadIdx.x;
        if (idx >= TN) return;
        int t = idx / NN;
        int n = idx - t * NN;
        int type = nt[idx];
        float r = req[idx];
        float xv[5];
        xv[0] = __ldg(&emb[type * 3 + 0]);
        xv[1] = __ldg(&emb[type * 3 + 1]);
        xv[2] = __ldg(&emb[type * 3 + 2]);
        xv[3] = (n < NLOCK) ? r : (r - smean[t]) * srstd[t];
        xv[4] = ti[idx];

        float h[12];
        #pragma unroll
        for (int j = 0; j < 12; j++) {
            float a = 0.f;
            #pragma unroll
            for (int k = 0; k < 5; k++) a = fmaf(xv[k], sW[k * 12 + j], a);
            h[j] = a;
        }
        float es0 = 0.f, es1 = 0.f, ed0 = 0.f, ed1 = 0.f;
        #pragma unroll
        for (int c = 0; c < 6; c++) {
            es0 = fmaf(h[c],     sas[c],     es0);
            es1 = fmaf(h[6 + c], sas[6 + c], es1);
            ed0 = fmaf(h[c],     sad[c],     ed0);
            ed1 = fmaf(h[6 + c], sad[6 + c], ed1);
        }
        g_rowA[(size_t)idx * 2]     = make_float4(es0, pk2(h[0], h[1]), pk2(h[2], h[3]), pk2(h[4], h[5]));
        g_rowA[(size_t)idx * 2 + 1] = make_float4(es1, pk2(h[6], h[7]), pk2(h[8], h[9]), pk2(h[10], h[11]));
        g_edA[idx] = make_float2(ed0, ed1);
    }
}

// ---------------- fused gather + softmax + (bias/relu) + next projection ----------
// 8 lanes per node: lane = head*4 + slot (stride-4 interleave, unroll 4).
// Each lane loads ONE self-contained 16B head-half per edge (1 LDG.128); head
// pair hits same 128B line -> 1 L1tex wavefront per edge. No intra-loop shfls.
template <bool FINAL, bool A_TO_B>
__global__ void gather_kernel(const float* __restrict__ bcur,
                              const float* __restrict__ Wn,
                              const float* __restrict__ asn,
                              const float* __restrict__ adn,
                              float* __restrict__ outp) {
    __shared__ float sW[144], sas[12], sad[12], sb[12];
    if (!FINAL) {
        for (int k = threadIdx.x; k < 144; k += blockDim.x) sW[k] = Wn[k];
        if (threadIdx.x < 12) { sas[threadIdx.x] = asn[threadIdx.x]; sad[threadIdx.x] = adn[threadIdx.x]; }
    }
    if (threadIdx.x < 12) sb[threadIdx.x] = bcur[threadIdx.x];
    __syncthreads();

    const float4* rows_in  = A_TO_B ? g_rowA : g_rowB;
    const float2* ed_in    = A_TO_B ? g_edA  : g_edB;
    float4*       rows_out = A_TO_B ? g_rowB : g_rowA;
    float2*       ed_out   = A_TO_B ? g_edB  : g_edA;

    int gt   = blockIdx.x * blockDim.x + threadIdx.x;
    int i    = gt >> 3;                    // global node
    int lane = gt & 7;
    int head = lane >> 2;                  // 0 or 1
    int slot = lane & 3;                   // stride-4 slot
    int t    = i / NN;
    int nloc = i - t * NN;
    const float4* tbase = rows_in + (size_t)t * NN * 2 + head;

    float2 edv = ed_in[i];
    float ed_mine = head ? edv.y : edv.x;

    float a0 = 0.f, a1 = 0.f, a2 = 0.f, a3 = 0.f, a4 = 0.f, a5 = 0.f, aden = 0.f;

    auto process = [&](int src) {
        float4 q = tbase[(size_t)src * 2];
        float p = __expf(lrelu(q.x + ed_mine));
        float2 u = up2(q.y), v = up2(q.z), w = up2(q.w);
        a0 = fmaf(u.x, p, a0); a1 = fmaf(u.y, p, a1);
        a2 = fmaf(v.x, p, a2); a3 = fmaf(v.y, p, a3);
        a4 = fmaf(w.x, p, a4); a5 = fmaf(w.y, p, a5);
        aden += p;
    };

    int cnt = g_cnt[i];
    const int* bkt = &g_bkt[(size_t)i * CAP];

    if (slot == 0) process(nloc);          // self loop

    #pragma unroll 4
    for (int j = slot; j < cnt; j += 4) {
        process(bkt[j]);
    }

    // reduce within the 4 slots of this head
    #pragma unroll
    for (int o2 = 1; o2 < 4; o2 <<= 1) {
        a0 += __shfl_xor_sync(0xFFFFFFFFu, a0, o2);
        a1 += __shfl_xor_sync(0xFFFFFFFFu, a1, o2);
        a2 += __shfl_xor_sync(0xFFFFFFFFu, a2, o2);
        a3 += __shfl_xor_sync(0xFFFFFFFFu, a3, o2);
        a4 += __shfl_xor_sync(0xFFFFFFFFu, a4, o2);
        a5 += __shfl_xor_sync(0xFFFFFFFFu, a5, o2);
        aden += __shfl_xor_sync(0xFFFFFFFFu, aden, o2);
    }
    // exchange heads (xor 4)
    float b0 = __shfl_xor_sync(0xFFFFFFFFu, a0, 4);
    float b1 = __shfl_xor_sync(0xFFFFFFFFu, a1, 4);
    float b2 = __shfl_xor_sync(0xFFFFFFFFu, a2, 4);
    float b3 = __shfl_xor_sync(0xFFFFFFFFu, a3, 4);
    float b4 = __shfl_xor_sync(0xFFFFFFFFu, a4, 4);
    float b5 = __shfl_xor_sync(0xFFFFFFFFu, a5, 4);
    float bden = __shfl_xor_sync(0xFFFFFFFFu, aden, 4);

    float num[12], den0, den1;
    if (head == 0) {
        num[0]=a0; num[1]=a1; num[2]=a2; num[3]=a3; num[4]=a4; num[5]=a5;
        num[6]=b0; num[7]=b1; num[8]=b2; num[9]=b3; num[10]=b4; num[11]=b5;
        den0 = aden; den1 = bden;
    } else {
        num[0]=b0; num[1]=b1; num[2]=b2; num[3]=b3; num[4]=b4; num[5]=b5;
        num[6]=a0; num[7]=a1; num[8]=a2; num[9]=a3; num[10]=a4; num[11]=a5;
        den0 = bden; den1 = aden;
    }

    float r0 = 1.f / (den0 + 1e-16f);
    float r1 = 1.f / (den1 + 1e-16f);
    float o[12];
    #pragma unroll
    for (int k = 0; k < 12; k++) {
        float v = num[k] * ((k < 6) ? r0 : r1) + sb[k];
        o[k] = FINAL ? v : fmaxf(v, 0.f);
    }

    if (FINAL) {
        if (lane < 3) {
            float4* dp = (float4*)(outp + (size_t)i * 12);
            dp[lane] = make_float4(o[lane * 4], o[lane * 4 + 1], o[lane * 4 + 2], o[lane * 4 + 3]);
        }
    } else {
        // lanes 0..3 compute 3 output columns each (cols lane*3 .. lane*3+2)
        float hc[3] = {0.f, 0.f, 0.f};
        float es0 = 0.f, es1 = 0.f, ep0 = 0.f, ep1 = 0.f;
        if (lane < 4) {
            #pragma unroll
            for (int jj = 0; jj < 3; jj++) {
                int jc = lane * 3 + jj;
                float a = 0.f;
                #pragma unroll
                for (int k = 0; k < 12; k++) a = fmaf(o[k], sW[k * 12 + jc], a);
                hc[jj] = a;
                if (jc < 6) { es0 = fmaf(a, sas[jc], es0); ep0 = fmaf(a, sad[jc], ep0); }
                else        { es1 = fmaf(a, sas[jc], es1); ep1 = fmaf(a, sad[jc], ep1); }
            }
        }
        #pragma unroll
        for (int o2 = 1; o2 < 8; o2 <<= 1) {
            es0 += __shfl_xor_sync(0xFFFFFFFFu, es0, o2);
            es1 += __shfl_xor_sync(0xFFFFFFFFu, es1, o2);
            ep0 += __shfl_xor_sync(0xFFFFFFFFu, ep0, o2);
            ep1 += __shfl_xor_sync(0xFFFFFFFFu, ep1, o2);
        }
        // partner columns: lane0 gets lane1's cols 3-5; lane2 gets lane3's cols 9-11
        float q0 = __shfl_xor_sync(0xFFFFFFFFu, hc[0], 1);
        float q1 = __shfl_xor_sync(0xFFFFFFFFu, hc[1], 1);
        float q2 = __shfl_xor_sync(0xFFFFFFFFu, hc[2], 1);

        if (lane == 0) {
            rows_out[(size_t)i * 2] = make_float4(es0, pk2(hc[0], hc[1]),
                                                  pk2(hc[2], q0), pk2(q1, q2));
        } else if (lane == 2) {
            rows_out[(size_t)i * 2 + 1] = make_float4(es1, pk2(hc[0], hc[1]),
                                                      pk2(hc[2], q0), pk2(q1, q2));
        } else if (lane == 4) {
            ed_out[i] = make_float2(ep0, ep1);
        }
    }
}

// ---------------- launch ----------------
extern "C" void kernel_launch(void* const* d_in, const int* in_sizes, int n_in,
                              void* d_out, int out_size) {
    const int*   node_types = (const int*)d_in[0];
    const float* requests   = (const float*)d_in[1];
    const float* time_index = (const float*)d_in[2];
    const int*   edge_index = (const int*)d_in[3];
    const float* emb        = (const float*)d_in[4];
    float* out = (float*)d_out;

    const int BT = 256;
    const int zero_blocks = (TN / 4 + BT - 1) / BT;                 // 391
    const int mega_blocks = RED_BLOCKS + SC_BLOCKS + NODE0_BLOCKS;  // 8327
    const int gather_blocks = (TN * 8) / BT;                        // 12500 exact

    zero_kernel<<<zero_blocks, BT>>>();
    mega_kernel<<<mega_blocks, BT>>>(edge_index, requests, node_types, time_index,
                                     emb, (const float*)d_in[5],
                                     (const float*)d_in[6], (const float*)d_in[7]);

    gather_kernel<false, true ><<<gather_blocks, BT>>>(
        (const float*)d_in[8],  (const float*)d_in[9],
        (const float*)d_in[10], (const float*)d_in[11], nullptr);
    gather_kernel<false, false><<<gather_blocks, BT>>>(
        (const float*)d_in[12], (const float*)d_in[13],
        (const float*)d_in[14], (const float*)d_in[15], nullptr);
    gather_kernel<false, true ><<<gather_blocks, BT>>>(
        (const float*)d_in[16], (const float*)d_in[17],
        (const float*)d_in[18], (const float*)d_in[19], nullptr);
    gather_kernel<true,  false><<<gather_blocks, BT>>>(
        (const float*)d_in[20], nullptr, nullptr, nullptr, out);
}

// round 14
// speedup vs baseline: 1.5650x; 1.0244x over previous
#include <cuda_runtime.h>
#include <cuda_fp16.h>
#include <math.h>

#define NN 100000
#define EE 1600000
#define TT 4
#define NLOCK 15
#define TN (TT * NN)
#define CAP 64            // bucket capacity; P(Poisson(16) >= 64) ~ 2e-18

// ---------------- static device scratch ----------------
// Node row = 32B, split into two SELF-CONTAINED 16B head-halves:
//   row[2i+h] = { es_h (fp32), h_{6h+0..1}, h_{6h+2..3}, h_{6h+4..5} (fp16 pairs) }
__device__ float4 g_rowA[TN * 2];
__device__ float4 g_rowB[TN * 2];
__device__ float2 g_edA[TN];
__device__ float2 g_edB[TN];
__device__ int    g_cnt[TN];
__device__ int    g_bkt[(size_t)TN * CAP];   // padded per-(t,node) src buckets
__device__ double g_sum[TT];
__device__ double g_sumsq[TT];
__device__ int    g_done;                    // reduce-blocks completion counter

__device__ __forceinline__ float lrelu(float x) { return x > 0.f ? x : 0.2f * x; }

__device__ __forceinline__ float2 up2(float f) {
    unsigned u = __float_as_uint(f);
    __half2 h = *reinterpret_cast<__half2*>(&u);
    return __half22float2(h);
}
__device__ __forceinline__ float pk2(float a, float b) {
    __half2 h = __floats2half2_rn(a, b);
    return __uint_as_float(*reinterpret_cast<unsigned*>(&h));
}

// ---------------- zero: cnt (vectorized) + stats + done flag ----------------
__global__ void zero_kernel() {
    int i = blockIdx.x * blockDim.x + threadIdx.x;
    if (i < TN / 4) ((int4*)g_cnt)[i] = make_int4(0, 0, 0, 0);
    if (i < TT) { g_sum[i] = 0.0; g_sumsq[i] = 0.0; }
    if (i == 8) g_done = 0;
}

// ---------------- mega kernel: reduce + scatter + node0 (role-split) ----------
#define RED_BLOCKS 512           // 128 blocks x TT timesteps
#define SC_BLOCKS_PER_T 1563     // ceil(EE/4 / 256)
#define SC_BLOCKS (SC_BLOCKS_PER_T * TT)
#define NODE0_BLOCKS 1563        // ceil(TN / 256)
__global__ void mega_kernel(const int* __restrict__ ei,
                            const float* __restrict__ req,
                            const int* __restrict__ nt,
                            const float* __restrict__ ti,
                            const float* __restrict__ emb,
                            const float* __restrict__ W,
                            const float* __restrict__ as_,
                            const float* __restrict__ ad_) {
    if (blockIdx.x < RED_BLOCKS) {
        // ---- reduce role ----
        const int t = blockIdx.x >> 7;            // 128 blocks per t
        const int bx = blockIdx.x & 127;
        const int M = NN - NLOCK;
        double s = 0.0, ss = 0.0;
        for (int i = bx * blockDim.x + threadIdx.x; i < M; i += 128 * blockDim.x) {
            double v = (double)req[t * NN + NLOCK + i];
            s += v; ss += v * v;
        }
        #pragma unroll
        for (int o = 16; o > 0; o >>= 1) {
            s  += __shfl_down_sync(0xFFFFFFFFu, s,  o);
            ss += __shfl_down_sync(0xFFFFFFFFu, ss, o);
        }
        __shared__ double shs[8], shss[8];
        int w = threadIdx.x >> 5, l = threadIdx.x & 31;
        if (l == 0) { shs[w] = s; shss[w] = ss; }
        __syncthreads();
        if (threadIdx.x == 0) {
            double S = 0.0, SS = 0.0;
            int nw = blockDim.x >> 5;
            for (int i = 0; i < nw; i++) { S += shs[i]; SS += shss[i]; }
            atomicAdd(&g_sum[t], S);
            atomicAdd(&g_sumsq[t], SS);
            __threadfence();
            atomicAdd(&g_done, 1);
        }
    } else if (blockIdx.x < RED_BLOCKS + SC_BLOCKS) {
        // ---- scatter role: 4 edges/thread ----
        int sblk = blockIdx.x - RED_BLOCKS;
        int t = sblk / SC_BLOCKS_PER_T;
        int q = (sblk - t * SC_BLOCKS_PER_T) * blockDim.x + threadIdx.x;
        if (q >= EE / 4) return;
        const int* b = ei + (size_t)t * 2 * EE;
        int4 s4 = *(const int4*)(b + q * 4);
        int4 d4 = *(const int4*)(b + EE + q * 4);
        int g0 = t * NN + d4.x, g1 = t * NN + d4.y, g2 = t * NN + d4.z, g3 = t * NN + d4.w;
        int p0 = atomicAdd(&g_cnt[g0], 1);
        int p1 = atomicAdd(&g_cnt[g1], 1);
        int p2 = atomicAdd(&g_cnt[g2], 1);
        int p3 = atomicAdd(&g_cnt[g3], 1);
        g_bkt[(size_t)g0 * CAP + p0] = s4.x;
        g_bkt[(size_t)g1 * CAP + p1] = s4.y;
        g_bkt[(size_t)g2 * CAP + p2] = s4.z;
        g_bkt[(size_t)g3 * CAP + p3] = s4.w;
    } else {
        // ---- node0 role: layer-0 projection ----
        __shared__ float sW[5 * 12];
        __shared__ float sas[12], sad[12];
        __shared__ float smean[TT], srstd[TT];

        if (threadIdx.x == 0) {
            while (atomicAdd(&g_done, 0) < RED_BLOCKS) { __nanosleep(200); }
        }
        __syncthreads();
        __threadfence();

        for (int i = threadIdx.x; i < 5 * 12; i += blockDim.x) sW[i] = W[i];
        if (threadIdx.x < 12) { sas[threadIdx.x] = as_[threadIdx.x]; sad[threadIdx.x] = ad_[threadIdx.x]; }
        if (threadIdx.x < TT) {
            int t = threadIdx.x;
            double n = (double)(NN - NLOCK);
            double mean = g_sum[t] / n;
            double var = (g_sumsq[t] - g_sum[t] * mean) / (n - 1.0);
            smean[t] = (float)mean;
            srstd[t] = (float)(1.0 / sqrt(var));
        }
        __syncthreads();

        int nb = blockIdx.x - RED_BLOCKS - SC_BLOCKS;
        int idx = nb * blockDim.x + threadIdx.x;
        if (idx >= TN) return;
        int t = idx / NN;
        int n = idx - t * NN;
        int type = nt[idx];
        float r = req[idx];
        float xv[5];
        xv[0] = __ldg(&emb[type * 3 + 0]);
        xv[1] = __ldg(&emb[type * 3 + 1]);
        xv[2] = __ldg(&emb[type * 3 + 2]);
        xv[3] = (n < NLOCK) ? r : (r - smean[t]) * srstd[t];
        xv[4] = ti[idx];

        float h[12];
        #pragma unroll
        for (int j = 0; j < 12; j++) {
            float a = 0.f;
            #pragma unroll
            for (int k = 0; k < 5; k++) a = fmaf(xv[k], sW[k * 12 + j], a);
            h[j] = a;
        }
        float es0 = 0.f, es1 = 0.f, ed0 = 0.f, ed1 = 0.f;
        #pragma unroll
        for (int c = 0; c < 6; c++) {
            es0 = fmaf(h[c],     sas[c],     es0);
            es1 = fmaf(h[6 + c], sas[6 + c], es1);
            ed0 = fmaf(h[c],     sad[c],     ed0);
            ed1 = fmaf(h[6 + c], sad[6 + c], ed1);
        }
        g_rowA[(size_t)idx * 2]     = make_float4(es0, pk2(h[0], h[1]), pk2(h[2], h[3]), pk2(h[4], h[5]));
        g_rowA[(size_t)idx * 2 + 1] = make_float4(es1, pk2(h[6], h[7]), pk2(h[8], h[9]), pk2(h[10], h[11]));
        g_edA[idx] = make_float2(ed0, ed1);
    }
}

// ---------------- fused gather + softmax + (bias/relu) + next projection ----------
// 8 lanes per node: lane = head*4 + slot. Slot s owns bucket quads s, s+4, ...
// (int4 index loads: 4 edges per LDG.128, 4 row-loads batched -> MLP=4).
// Numerator products accumulate in half2 PER SLOT (<=5-6 edges -> fp16 error
// ~1e-4 of the partial), widened to fp32 once post-loop; reductions stay fp32.
template <bool FINAL, bool A_TO_B>
__global__ void gather_kernel(const float* __restrict__ bcur,
                              const float* __restrict__ Wn,
                              const float* __restrict__ asn,
                              const float* __restrict__ adn,
                              float* __restrict__ outp) {
    __shared__ float sW[144], sas[12], sad[12], sb[12];
    if (!FINAL) {
        for (int k = threadIdx.x; k < 144; k += blockDim.x) sW[k] = Wn[k];
        if (threadIdx.x < 12) { sas[threadIdx.x] = asn[threadIdx.x]; sad[threadIdx.x] = adn[threadIdx.x]; }
    }
    if (threadIdx.x < 12) sb[threadIdx.x] = bcur[threadIdx.x];
    __syncthreads();

    const float4* rows_in  = A_TO_B ? g_rowA : g_rowB;
    const float2* ed_in    = A_TO_B ? g_edA  : g_edB;
    float4*       rows_out = A_TO_B ? g_rowB : g_rowA;
    float2*       ed_out   = A_TO_B ? g_edB  : g_edA;

    int gt   = blockIdx.x * blockDim.x + threadIdx.x;
    int i    = gt >> 3;                    // global node
    int lane = gt & 7;
    int head = lane >> 2;                  // 0 or 1
    int slot = lane & 3;                   // quad selector
    int t    = i / NN;
    int nloc = i - t * NN;
    const float4* tbase = rows_in + (size_t)t * NN * 2 + head;

    float2 edv = ed_in[i];
    float ed_mine = head ? edv.y : edv.x;

    __half2 acc01 = __floats2half2_rn(0.f, 0.f);
    __half2 acc23 = acc01, acc45 = acc01;
    float aden = 0.f;

    auto procq = [&](float4 q) {
        float p = __expf(lrelu(q.x + ed_mine));
        __half2 ph = __float2half2_rn(p);
        acc01 = __hfma2(*(const __half2*)&q.y, ph, acc01);
        acc23 = __hfma2(*(const __half2*)&q.z, ph, acc23);
        acc45 = __hfma2(*(const __half2*)&q.w, ph, acc45);
        aden += p;
    };

    int cnt = g_cnt[i];
    const int4* bkt4 = (const int4*)&g_bkt[(size_t)i * CAP];

    if (slot == 0) procq(tbase[(size_t)nloc * 2]);     // self loop

    for (int qi = slot; qi * 4 < cnt; qi += 4) {
        int4 iv = bkt4[qi];
        int rem = cnt - qi * 4;
        if (rem >= 4) {
            float4 qa = tbase[(size_t)iv.x * 2];
            float4 qb = tbase[(size_t)iv.y * 2];
            float4 qc = tbase[(size_t)iv.z * 2];
            float4 qd = tbase[(size_t)iv.w * 2];
            procq(qa); procq(qb); procq(qc); procq(qd);
        } else {
            procq(tbase[(size_t)iv.x * 2]);
            if (rem > 1) procq(tbase[(size_t)iv.y * 2]);
            if (rem > 2) procq(tbase[(size_t)iv.z * 2]);
        }
    }

    // widen per-slot partials to fp32 once
    float2 f01 = __half22float2(acc01);
    float2 f23 = __half22float2(acc23);
    float2 f45 = __half22float2(acc45);
    float a0 = f01.x, a1 = f01.y, a2 = f23.x, a3 = f23.y, a4 = f45.x, a5 = f45.y;

    // reduce within the 4 slots of this head (fp32)
    #pragma unroll
    for (int o2 = 1; o2 < 4; o2 <<= 1) {
        a0 += __shfl_xor_sync(0xFFFFFFFFu, a0, o2);
        a1 += __shfl_xor_sync(0xFFFFFFFFu, a1, o2);
        a2 += __shfl_xor_sync(0xFFFFFFFFu, a2, o2);
        a3 += __shfl_xor_sync(0xFFFFFFFFu, a3, o2);
        a4 += __shfl_xor_sync(0xFFFFFFFFu, a4, o2);
        a5 += __shfl_xor_sync(0xFFFFFFFFu, a5, o2);
        aden += __shfl_xor_sync(0xFFFFFFFFu, aden, o2);
    }
    // exchange heads (xor 4)
    float b0 = __shfl_xor_sync(0xFFFFFFFFu, a0, 4);
    float b1 = __shfl_xor_sync(0xFFFFFFFFu, a1, 4);
    float b2 = __shfl_xor_sync(0xFFFFFFFFu, a2, 4);
    float b3 = __shfl_xor_sync(0xFFFFFFFFu, a3, 4);
    float b4 = __shfl_xor_sync(0xFFFFFFFFu, a4, 4);
    float b5 = __shfl_xor_sync(0xFFFFFFFFu, a5, 4);
    float bden = __shfl_xor_sync(0xFFFFFFFFu, aden, 4);

    float num[12], den0, den1;
    if (head == 0) {
        num[0]=a0; num[1]=a1; num[2]=a2; num[3]=a3; num[4]=a4; num[5]=a5;
        num[6]=b0; num[7]=b1; num[8]=b2; num[9]=b3; num[10]=b4; num[11]=b5;
        den0 = aden; den1 = bden;
    } else {
        num[0]=b0; num[1]=b1; num[2]=b2; num[3]=b3; num[4]=b4; num[5]=b5;
        num[6]=a0; num[7]=a1; num[8]=a2; num[9]=a3; num[10]=a4; num[11]=a5;
        den0 = bden; den1 = aden;
    }

    float r0 = 1.f / (den0 + 1e-16f);
    float r1 = 1.f / (den1 + 1e-16f);
    float o[12];
    #pragma unroll
    for (int k = 0; k < 12; k++) {
        float v = num[k] * ((k < 6) ? r0 : r1) + sb[k];
        o[k] = FINAL ? v : fmaxf(v, 0.f);
    }

    if (FINAL) {
        if (lane < 3) {
            float4* dp = (float4*)(outp + (size_t)i * 12);
            dp[lane] = make_float4(o[lane * 4], o[lane * 4 + 1], o[lane * 4 + 2], o[lane * 4 + 3]);
        }
    } else {
        // lanes 0..3 compute 3 output columns each (cols lane*3 .. lane*3+2)
        float hc[3] = {0.f, 0.f, 0.f};
        float es0 = 0.f, es1 = 0.f, ep0 = 0.f, ep1 = 0.f;
        if (lane < 4) {
            #pragma unroll
            for (int jj = 0; jj < 3; jj++) {
                int jc = lane * 3 + jj;
                float a = 0.f;
                #pragma unroll
                for (int k = 0; k < 12; k++) a = fmaf(o[k], sW[k * 12 + jc], a);
                hc[jj] = a;
                if (jc < 6) { es0 = fmaf(a, sas[jc], es0); ep0 = fmaf(a, sad[jc], ep0); }
                else        { es1 = fmaf(a, sas[jc], es1); ep1 = fmaf(a, sad[jc], ep1); }
            }
        }
        #pragma unroll
        for (int o2 = 1; o2 < 8; o2 <<= 1) {
            es0 += __shfl_xor_sync(0xFFFFFFFFu, es0, o2);
            es1 += __shfl_xor_sync(0xFFFFFFFFu, es1, o2);
            ep0 += __shfl_xor_sync(0xFFFFFFFFu, ep0, o2);
            ep1 += __shfl_xor_sync(0xFFFFFFFFu, ep1, o2);
        }
        // partner columns: lane0 gets lane1's cols 3-5; lane2 gets lane3's cols 9-11
        float q0 = __shfl_xor_sync(0xFFFFFFFFu, hc[0], 1);
        float q1 = __shfl_xor_sync(0xFFFFFFFFu, hc[1], 1);
        float q2 = __shfl_xor_sync(0xFFFFFFFFu, hc[2], 1);

        if (lane == 0) {
            rows_out[(size_t)i * 2] = make_float4(es0, pk2(hc[0], hc[1]),
                                                  pk2(hc[2], q0), pk2(q1, q2));
        } else if (lane == 2) {
            rows_out[(size_t)i * 2 + 1] = make_float4(es1, pk2(hc[0], hc[1]),
                                                      pk2(hc[2], q0), pk2(q1, q2));
        } else if (lane == 4) {
            ed_out[i] = make_float2(ep0, ep1);
        }
    }
}

// ---------------- launch ----------------
extern "C" void kernel_launch(void* const* d_in, const int* in_sizes, int n_in,
                              void* d_out, int out_size) {
    const int*   node_types = (const int*)d_in[0];
    const float* requests   = (const float*)d_in[1];
    const float* time_index = (const float*)d_in[2];
    const int*   edge_index = (const int*)d_in[3];
    const float* emb        = (const float*)d_in[4];
    float* out = (float*)d_out;

    const int BT = 256;
    const int zero_blocks = (TN / 4 + BT - 1) / BT;                 // 391
    const int mega_blocks = RED_BLOCKS + SC_BLOCKS + NODE0_BLOCKS;  // 8327
    const int gather_blocks = (TN * 8) / BT;                        // 12500 exact

    zero_kernel<<<zero_blocks, BT>>>();
    mega_kernel<<<mega_blocks, BT>>>(edge_index, requests, node_types, time_index,
                                     emb, (const float*)d_in[5],
                                     (const float*)d_in[6], (const float*)d_in[7]);

    gather_kernel<false, true ><<<gather_blocks, BT>>>(
        (const float*)d_in[8],  (const float*)d_in[9],
        (const float*)d_in[10], (const float*)d_in[11], nullptr);
    gather_kernel<false, false><<<gather_blocks, BT>>>(
        (const float*)d_in[12], (const float*)d_in[13],
        (const float*)d_in[14], (const float*)d_in[15], nullptr);
    gather_kernel<false, true ><<<gather_blocks, BT>>>(
        (const float*)d_in[16], (const float*)d_in[17],
        (const float*)d_in[18], (const float*)d_in[19], nullptr);
    gather_kernel<true,  false><<<gather_blocks, BT>>>(
        (const float*)d_in[20], nullptr, nullptr, nullptr, out);
}